// round 1
// baseline (speedup 1.0000x reference)
#include <cuda_runtime.h>

#define TB 4
#define TS 2048
#define TH 16
#define TD 64
#define TC 1024

// Scratch (alloc-free rule: __device__ globals)
static __device__ float g_qkv[(size_t)8192 * 3072];   // [B*S, 3*C]
static __device__ float g_ctx[(size_t)8192 * 1024];   // [B*S, C]
static __device__ float g_entpad[4];                  // fallback entropy sink

// ---------------------------------------------------------------------------
// SGEMM: C[M,N] = A[M,K] @ B[K,N], tiles 128x128x8, 256 thr, 8x8 microtile.
// M,N,K assumed multiples of tile dims (true here).
// ---------------------------------------------------------------------------
__global__ __launch_bounds__(256, 2) void sgemm_kernel(
    const float* __restrict__ A, const float* __restrict__ B,
    float* __restrict__ C, int M, int N, int K)
{
    __shared__ float As[8][128];
    __shared__ float Bs[8][128];
    const int tid = threadIdx.x;
    const int tx = tid & 15;
    const int ty = tid >> 4;
    const int row0 = blockIdx.y << 7;
    const int col0 = blockIdx.x << 7;
    const int arow = tid >> 1;
    const int acol = (tid & 1) << 2;
    const int brow = tid >> 5;
    const int bcol = (tid & 31) << 2;

    const float* Ap = A + (size_t)(row0 + arow) * K + acol;
    const float* Bp = B + (size_t)brow * N + col0 + bcol;

    float acc[8][8];
#pragma unroll
    for (int i = 0; i < 8; ++i)
#pragma unroll
        for (int j = 0; j < 8; ++j) acc[i][j] = 0.f;

    for (int k0 = 0; k0 < K; k0 += 8) {
        float4 av = *(const float4*)(Ap + k0);
        float4 bv = *(const float4*)(Bp + (size_t)k0 * N);
        As[acol + 0][arow] = av.x;
        As[acol + 1][arow] = av.y;
        As[acol + 2][arow] = av.z;
        As[acol + 3][arow] = av.w;
        *(float4*)&Bs[brow][bcol] = bv;
        __syncthreads();
#pragma unroll
        for (int kc = 0; kc < 8; ++kc) {
            float a[8], b[8];
            *(float4*)&a[0] = *(const float4*)&As[kc][ty << 3];
            *(float4*)&a[4] = *(const float4*)&As[kc][(ty << 3) + 4];
            *(float4*)&b[0] = *(const float4*)&Bs[kc][tx << 3];
            *(float4*)&b[4] = *(const float4*)&Bs[kc][(tx << 3) + 4];
#pragma unroll
            for (int i = 0; i < 8; ++i)
#pragma unroll
                for (int j = 0; j < 8; ++j)
                    acc[i][j] = fmaf(a[i], b[j], acc[i][j]);
        }
        __syncthreads();
    }
#pragma unroll
    for (int i = 0; i < 8; ++i) {
        float* cp = C + (size_t)(row0 + (ty << 3) + i) * N + col0 + (tx << 3);
        *(float4*)cp = make_float4(acc[i][0], acc[i][1], acc[i][2], acc[i][3]);
        *(float4*)(cp + 4) = make_float4(acc[i][4], acc[i][5], acc[i][6], acc[i][7]);
    }
}

// ---------------------------------------------------------------------------
// LayerNorm over head_dim=64 for q and k slices of qkv, in place.
// One warp per row; lane holds 2 elements.
// ---------------------------------------------------------------------------
__global__ __launch_bounds__(256) void ln_kernel(
    float* __restrict__ qkv,
    const float* __restrict__ qs, const float* __restrict__ qb,
    const float* __restrict__ ks, const float* __restrict__ kb)
{
    const int w = (int)((blockIdx.x * 256u + threadIdx.x) >> 5);
    const int lane = threadIdx.x & 31;
    const int NQ = TB * TS * TH;             // 131072 q rows, then 131072 k rows
    if (w >= 2 * NQ) return;
    const bool isK = w >= NQ;
    const int r = isK ? (w - NQ) : w;
    const int h = r & 15;
    const int bs = r >> 4;
    float* p = qkv + (size_t)bs * 3072 + (isK ? 1024 : 0) + h * 64 + lane * 2;
    const float* sc = (isK ? ks : qs) + lane * 2;
    const float* bi = (isK ? kb : qb) + lane * 2;

    float2 v = *(const float2*)p;
    float s = v.x + v.y;
    float sq = v.x * v.x + v.y * v.y;
#pragma unroll
    for (int off = 16; off; off >>= 1) {
        s  += __shfl_xor_sync(0xffffffffu, s, off);
        sq += __shfl_xor_sync(0xffffffffu, sq, off);
    }
    float mean = s * (1.f / 64.f);
    float var = fmaxf(sq * (1.f / 64.f) - mean * mean, 0.f);
    float rstd = rsqrtf(var + 1e-5f);
    float2 o;
    o.x = (v.x - mean) * rstd * sc[0] + bi[0];
    o.y = (v.y - mean) * rstd * sc[1] + bi[1];
    *(float2*)p = o;
}

__global__ void zero4_kernel(float* p) { p[threadIdx.x] = 0.f; }

// ---------------------------------------------------------------------------
// Flash attention + streaming entropy.
// Grid (S/64, H, B), 256 threads as 16x16 (ty=q-group, tx=k/d-group), 4x4 micro.
// Qt/Kt stored d-major with group-XOR swizzle -> conflict-free LDS.128 reads.
// P overlays the Kt buffer (48KB static smem total).
// Entropy: -sum a log a = log(l) - T/l, T = sum p*(s-m), streamed.
// ---------------------------------------------------------------------------
__global__ __launch_bounds__(256) void attn_kernel(
    const float* __restrict__ qkv, float* __restrict__ ctx, float* __restrict__ ent)
{
    __shared__ float Qt[4096];
    __shared__ float KP[4096];   // K^T (swizzled), then reused as P[q][k]
    __shared__ float Vs[4096];   // V[k][d], reused as entropy-reduce scratch

    const int tid = threadIdx.x;
    const int tx = tid & 15;
    const int ty = tid >> 4;
    const int qb0 = blockIdx.x << 6;
    const int h = blockIdx.y;
    const int b = blockIdx.z;
    const float inv = 0.125f;    // 1/sqrt(64), TEMP=1

    const size_t base = (size_t)b * TS * 3072 + h * 64;

    // Load Q tile, transposed + swizzled, pre-scaled by inv
    {
        const int r = tid >> 4;
        const int d0 = (tid & 15) << 2;
#pragma unroll
        for (int rr = 0; rr < 4; ++rr) {
            int row = (rr << 4) + r;
            float4 v = *(const float4*)(qkv + base + (size_t)(qb0 + row) * 3072 + d0);
            int g = row >> 2, ri = row & 3;
            Qt[(d0 + 0) * 64 + ((g ^ ((d0 + 0) & 15)) << 2) + ri] = v.x * inv;
            Qt[(d0 + 1) * 64 + ((g ^ ((d0 + 1) & 15)) << 2) + ri] = v.y * inv;
            Qt[(d0 + 2) * 64 + ((g ^ ((d0 + 2) & 15)) << 2) + ri] = v.z * inv;
            Qt[(d0 + 3) * 64 + ((g ^ ((d0 + 3) & 15)) << 2) + ri] = v.w * inv;
        }
    }

    float o[4][4];
    float m[4], l[4], Tacc[4];
#pragma unroll
    for (int i = 0; i < 4; ++i) {
        m[i] = -1e30f; l[i] = 0.f; Tacc[i] = 0.f;
#pragma unroll
        for (int j = 0; j < 4; ++j) o[i][j] = 0.f;
    }

    for (int kt = 0; kt < TS / 64; ++kt) {
        __syncthreads();   // protect KP(P)/Vs from previous iter's PV readers
        // Load K^T (swizzled) + V tiles
        {
            const int r = tid >> 4;
            const int d0 = (tid & 15) << 2;
#pragma unroll
            for (int rr = 0; rr < 4; ++rr) {
                int row = (rr << 4) + r;
                const float* gp = qkv + base + (size_t)(kt * 64 + row) * 3072 + d0;
                float4 kv = *(const float4*)(gp + 1024);
                float4 vv = *(const float4*)(gp + 2048);
                int g = row >> 2, ri = row & 3;
                KP[(d0 + 0) * 64 + ((g ^ ((d0 + 0) & 15)) << 2) + ri] = kv.x;
                KP[(d0 + 1) * 64 + ((g ^ ((d0 + 1) & 15)) << 2) + ri] = kv.y;
                KP[(d0 + 2) * 64 + ((g ^ ((d0 + 2) & 15)) << 2) + ri] = kv.z;
                KP[(d0 + 3) * 64 + ((g ^ ((d0 + 3) & 15)) << 2) + ri] = kv.w;
                *(float4*)&Vs[row * 64 + d0] = vv;
            }
        }
        __syncthreads();

        // S = (Q*inv) K^T   (4x4 per thread)
        float s4[4][4];
#pragma unroll
        for (int i = 0; i < 4; ++i)
#pragma unroll
            for (int j = 0; j < 4; ++j) s4[i][j] = 0.f;

#pragma unroll 8
        for (int d = 0; d < 64; ++d) {
            float4 aq = *(const float4*)&Qt[d * 64 + ((ty ^ (d & 15)) << 2)];
            float4 bk = *(const float4*)&KP[d * 64 + ((tx ^ (d & 15)) << 2)];
            float av[4] = {aq.x, aq.y, aq.z, aq.w};
            float bv[4] = {bk.x, bk.y, bk.z, bk.w};
#pragma unroll
            for (int i = 0; i < 4; ++i)
#pragma unroll
                for (int j = 0; j < 4; ++j)
                    s4[i][j] = fmaf(av[i], bv[j], s4[i][j]);
        }

        // Online softmax + entropy-term update (row state replicated over tx)
        float p4[4][4];
#pragma unroll
        for (int i = 0; i < 4; ++i) {
            float mm = fmaxf(fmaxf(s4[i][0], s4[i][1]), fmaxf(s4[i][2], s4[i][3]));
#pragma unroll
            for (int off = 8; off; off >>= 1)
                mm = fmaxf(mm, __shfl_xor_sync(0xffffffffu, mm, off));
            float mn = fmaxf(m[i], mm);
            float lsum = 0.f, tsum = 0.f;
#pragma unroll
            for (int j = 0; j < 4; ++j) {
                float dd = s4[i][j] - mn;
                float e = __expf(dd);
                p4[i][j] = e;
                lsum += e;
                tsum = fmaf(e, dd, tsum);
            }
#pragma unroll
            for (int off = 8; off; off >>= 1) {
                lsum += __shfl_xor_sync(0xffffffffu, lsum, off);
                tsum += __shfl_xor_sync(0xffffffffu, tsum, off);
            }
            float dm = mn - m[i];             // >= 0, finite*; -1e30 init keeps it finite
            float corr = __expf(-dm);
            Tacc[i] = fmaf(corr, Tacc[i] - dm * l[i], tsum);
            l[i] = fmaf(l[i], corr, lsum);
            m[i] = mn;
#pragma unroll
            for (int j = 0; j < 4; ++j) o[i][j] *= corr;
        }

        __syncthreads();   // all warps done reading Kt before overwrite with P
#pragma unroll
        for (int i = 0; i < 4; ++i)
            *(float4*)&KP[((ty << 2) + i) * 64 + (tx << 2)] =
                make_float4(p4[i][0], p4[i][1], p4[i][2], p4[i][3]);
        __syncthreads();

        // O += P @ V  (k in chunks of 4)
#pragma unroll 4
        for (int k0 = 0; k0 < 64; k0 += 4) {
            float4 pa[4], vb[4];
#pragma unroll
            for (int i = 0; i < 4; ++i)
                pa[i] = *(const float4*)&KP[((ty << 2) + i) * 64 + k0];
#pragma unroll
            for (int kk = 0; kk < 4; ++kk)
                vb[kk] = *(const float4*)&Vs[(k0 + kk) * 64 + (tx << 2)];
#pragma unroll
            for (int i = 0; i < 4; ++i) {
                float pav[4] = {pa[i].x, pa[i].y, pa[i].z, pa[i].w};
#pragma unroll
                for (int kk = 0; kk < 4; ++kk) {
                    float vbv[4] = {vb[kk].x, vb[kk].y, vb[kk].z, vb[kk].w};
#pragma unroll
                    for (int j = 0; j < 4; ++j)
                        o[i][j] = fmaf(pav[kk], vbv[j], o[i][j]);
                }
            }
        }
    }

    // Write context: ctx[b, q, h*64 + d]  (directly in [B,S,C] layout)
#pragma unroll
    for (int i = 0; i < 4; ++i) {
        float rl = 1.f / l[i];
        int q = qb0 + (ty << 2) + i;
        *(float4*)(ctx + (size_t)(b * TS + q) * 1024 + h * 64 + (tx << 2)) =
            make_float4(o[i][0] * rl, o[i][1] * rl, o[i][2] * rl, o[i][3] * rl);
    }

    // Entropy: per-row log(l) - T/l, CTA-reduce, one atomic per CTA
    __syncthreads();
    float* red = Vs;
    if (tx == 0) {
        float e = 0.f;
#pragma unroll
        for (int i = 0; i < 4; ++i) e += __logf(l[i]) - Tacc[i] / l[i];
        red[ty] = e;
    }
    __syncthreads();
    if (tid == 0) {
        float e = 0.f;
#pragma unroll
        for (int i = 0; i < 16; ++i) e += red[i];
        // mean over (H,S) and divide by log(S)
        const float ent_scale = (float)(1.0 / (7.6246189861593985 * (double)(TH * TS)));
        atomicAdd(ent + b, e * ent_scale);
    }
}

// ---------------------------------------------------------------------------
extern "C" void kernel_launch(void* const* d_in, const int* in_sizes, int n_in,
                              void* d_out, int out_size)
{
    const float* x       = (const float*)d_in[0];
    const float* w_qkv   = (const float*)d_in[1];
    const float* w_proj  = (const float*)d_in[2];
    const float* q_scale = (const float*)d_in[3];
    const float* q_bias  = (const float*)d_in[4];
    const float* k_scale = (const float*)d_in[5];
    const float* k_bias  = (const float*)d_in[6];
    float* out = (float*)d_out;

    float* qkv; cudaGetSymbolAddress((void**)&qkv, g_qkv);
    float* ctx; cudaGetSymbolAddress((void**)&ctx, g_ctx);
    float* entpad; cudaGetSymbolAddress((void**)&entpad, g_entpad);

    const int BS = TB * TS;                 // 8192
    const size_t main_elems = (size_t)BS * TC;
    float* ent = (out_size >= (int)(main_elems + TB)) ? (out + main_elems) : entpad;

    // 1) QKV projection: [8192,1024] @ [1024,3072]
    sgemm_kernel<<<dim3(3 * TC / 128, BS / 128), 256>>>(x, w_qkv, qkv, BS, 3 * TC, TC);

    // 2) LayerNorm q,k (262144 rows, 8 warps/block)
    ln_kernel<<<(2 * TB * TS * TH) / 8, 256>>>(qkv, q_scale, q_bias, k_scale, k_bias);

    // 3) zero entropy accumulators
    zero4_kernel<<<1, TB>>>(ent);

    // 4) fused attention + entropy -> ctx [B,S,C]
    attn_kernel<<<dim3(TS / 64, TH, TB), 256>>>(qkv, ctx, ent);

    // 5) output projection: [8192,1024] @ [1024,1024]
    sgemm_kernel<<<dim3(TC / 128, BS / 128), 256>>>(ctx, w_proj, out, BS, TC, TC);
}

// round 3
// speedup vs baseline: 1.3351x; 1.3351x over previous
#include <cuda_runtime.h>
#include <cuda_bf16.h>
#include <cstdint>

#define TB 4
#define TS 2048
#define TH 16
#define TD 64
#define TC 1024

// ---------------------------------------------------------------------------
// Scratch (alloc-free rule: __device__ globals)
// ---------------------------------------------------------------------------
static __device__ float g_qkv[(size_t)8192 * 3072];          // [B*S, 3*C] fp32
static __device__ float g_ctx[(size_t)8192 * 1024];          // [B*S, C]   fp32
static __device__ float g_entpad[4];
// bf16 split operands
static __device__ __nv_bfloat16 g_xh[(size_t)8192 * 1024];
static __device__ __nv_bfloat16 g_xl[(size_t)8192 * 1024];
static __device__ __nv_bfloat16 g_wqh[(size_t)3072 * 1024];  // w_qkv^T [N,K]
static __device__ __nv_bfloat16 g_wql[(size_t)3072 * 1024];
static __device__ __nv_bfloat16 g_ch[(size_t)8192 * 1024];
static __device__ __nv_bfloat16 g_cl[(size_t)8192 * 1024];
static __device__ __nv_bfloat16 g_wph[(size_t)1024 * 1024];  // w_proj^T [N,K]
static __device__ __nv_bfloat16 g_wpl[(size_t)1024 * 1024];

// ---------------------------------------------------------------------------
// Helpers (sm_103 base target: ldmatrix + mma.sync + cp.async only)
// ---------------------------------------------------------------------------
__device__ __forceinline__ uint32_t smem_u32(const void* p) {
    uint32_t a;
    asm("{ .reg .u64 t; cvta.to.shared.u64 t, %1; cvt.u32.u64 %0, t; }" : "=r"(a) : "l"(p));
    return a;
}
__device__ __forceinline__ uint32_t sw128(uint32_t off) { return off ^ ((off >> 3) & 0x70); }

__device__ __forceinline__ void cp16(uint32_t saddr, const void* gptr) {
    asm volatile("cp.async.cg.shared.global [%0], [%1], 16;" :: "r"(saddr), "l"(gptr));
}
__device__ __forceinline__ void cp_commit() {
    asm volatile("cp.async.commit_group;" ::: "memory");
}
template <int N>
__device__ __forceinline__ void cp_wait() {
    asm volatile("cp.async.wait_group %0;" :: "n"(N) : "memory");
}

__device__ __forceinline__ void ldm_x4(uint32_t addr, uint32_t r[4]) {
    asm volatile("ldmatrix.sync.aligned.m8n8.x4.shared.b16 {%0,%1,%2,%3}, [%4];"
                 : "=r"(r[0]), "=r"(r[1]), "=r"(r[2]), "=r"(r[3]) : "r"(addr));
}

__device__ __forceinline__ void mma16816(float d[4], const uint32_t a[4], const uint32_t b[2]) {
    asm volatile(
        "mma.sync.aligned.m16n8k16.row.col.f32.bf16.bf16.f32 "
        "{%0,%1,%2,%3}, {%4,%5,%6,%7}, {%8,%9}, {%0,%1,%2,%3};"
        : "+f"(d[0]), "+f"(d[1]), "+f"(d[2]), "+f"(d[3])
        : "r"(a[0]), "r"(a[1]), "r"(a[2]), "r"(a[3]), "r"(b[0]), "r"(b[1]));
}

// ---------------------------------------------------------------------------
// Split-precision conversion kernels
// ---------------------------------------------------------------------------
__device__ __forceinline__ void split_one(float v, __nv_bfloat16& h, __nv_bfloat16& l) {
    h = __float2bfloat16_rn(v);
    l = __float2bfloat16_rn(v - __bfloat162float(h));
}

__global__ __launch_bounds__(256) void split_kernel(
    const float4* __restrict__ in, __nv_bfloat16* __restrict__ hi,
    __nv_bfloat16* __restrict__ lo, int n4)
{
    int i = blockIdx.x * 256 + threadIdx.x;
    if (i >= n4) return;
    float4 v = in[i];
    float vs[4] = {v.x, v.y, v.z, v.w};
    __nv_bfloat16 h[4], l[4];
#pragma unroll
    for (int j = 0; j < 4; ++j) split_one(vs[j], h[j], l[j]);
    ushort4 hp, lp;
    hp.x = *(unsigned short*)&h[0]; hp.y = *(unsigned short*)&h[1];
    hp.z = *(unsigned short*)&h[2]; hp.w = *(unsigned short*)&h[3];
    lp.x = *(unsigned short*)&l[0]; lp.y = *(unsigned short*)&l[1];
    lp.z = *(unsigned short*)&l[2]; lp.w = *(unsigned short*)&l[3];
    ((ushort4*)hi)[i] = hp;
    ((ushort4*)lo)[i] = lp;
}

// Transpose + split: in f32 [K,N] -> hi/lo bf16 [N,K]
__global__ __launch_bounds__(256) void splitT_kernel(
    const float* __restrict__ in, __nv_bfloat16* __restrict__ hi,
    __nv_bfloat16* __restrict__ lo, int K, int N)
{
    __shared__ float t[32][33];
    const int n0 = blockIdx.x << 5;
    const int k0 = blockIdx.y << 5;
    const int tx = threadIdx.x, ty = threadIdx.y;   // 32 x 8
#pragma unroll
    for (int j = 0; j < 32; j += 8)
        t[ty + j][tx] = in[(size_t)(k0 + ty + j) * N + n0 + tx];
    __syncthreads();
#pragma unroll
    for (int j = 0; j < 32; j += 8) {
        float v = t[tx][ty + j];
        __nv_bfloat16 h, l;
        split_one(v, h, l);
        size_t o = (size_t)(n0 + ty + j) * K + k0 + tx;
        hi[o] = h;
        lo[o] = l;
    }
}

// ---------------------------------------------------------------------------
// Warp-MMA bf16x3 GEMM: C[M,N] fp32 = A[M,K] @ Bt[N,K]^T
// CTA tile 128x128, K-tile 64, 8 warps (2m x 4n), warp tile 64x32.
// cp.async double-buffered smem, SW128-swizzled rows (128B), ldmatrix feeds.
// D = Ah*Bh + Ah*Bl + Al*Bh  (fp32 accum) ~ fp32 precision.
// ---------------------------------------------------------------------------
#define GSM_AH 0
#define GSM_AL 16384
#define GSM_BH 32768
#define GSM_BL 49152
#define GSM_BUF 65536
#define GEMM_SMEM (2 * GSM_BUF)

__global__ __launch_bounds__(256) void gemm_mma_kernel(
    const __nv_bfloat16* __restrict__ Ah, const __nv_bfloat16* __restrict__ Al,
    const __nv_bfloat16* __restrict__ Bh, const __nv_bfloat16* __restrict__ Bl,
    float* __restrict__ C, int M, int N, int K)
{
    extern __shared__ char smem[];
    const uint32_t sb = smem_u32(smem);
    const int tid = threadIdx.x;
    const int wid = tid >> 5;
    const int lane = tid & 31;
    const int row0 = blockIdx.y << 7;
    const int col0 = blockIdx.x << 7;
    const int wm = (wid & 1) << 6;    // 0 or 64
    const int wn = (wid >> 1) << 5;   // 0,32,64,96

    // per-thread gmem/smem chunk mapping for the loader (4 chunks per array)
    const int lr0 = tid >> 1;          // rows: tid/2, chunks 0..7 split by (tid&1)
    const int lk0 = (tid & 1) << 2;    // chunk base 0 or 4

    float acc[4][4][4];
#pragma unroll
    for (int mt = 0; mt < 4; ++mt)
#pragma unroll
        for (int nt = 0; nt < 4; ++nt)
#pragma unroll
            for (int r = 0; r < 4; ++r) acc[mt][nt][r] = 0.f;

    const int nk = K >> 6;

    // ---- loader: one K64 tile (4 arrays) into buffer `buf` ----
    auto load_tile = [&](int kb, int buf) {
        const uint32_t s0 = sb + buf * GSM_BUF;
#pragma unroll
        for (int cc = 0; cc < 4; ++cc) {
            const int r = lr0;
            const int k8 = lk0 + cc;
            const size_t offA = (size_t)(row0 + r) * K + kb + (k8 << 3);
            const size_t offB = (size_t)(col0 + r) * K + kb + (k8 << 3);
            const uint32_t so = sw128((uint32_t)((r << 7) + (k8 << 4)));
            cp16(s0 + GSM_AH + so, Ah + offA);
            cp16(s0 + GSM_AL + so, Al + offA);
            cp16(s0 + GSM_BH + so, Bh + offB);
            cp16(s0 + GSM_BL + so, Bl + offB);
        }
        cp_commit();
    };

    load_tile(0, 0);

    // ldmatrix lane->address precompute
    const int la_r = lane & 15;          // A row within 16-row tile
    const int la_c = lane >> 4;          // A k-chunk offset (0/1)
    const int lb_r = ((lane >> 4) << 3) + (lane & 7);  // B row within 16-n tile
    const int lb_c = (lane >> 3) & 1;    // B k-chunk offset (0/1)

    for (int it = 0; it < nk; ++it) {
        if (it + 1 < nk) { load_tile((it + 1) << 6, (it + 1) & 1); cp_wait<1>(); }
        else             { cp_wait<0>(); }
        __syncthreads();
        const uint32_t s0 = sb + (it & 1) * GSM_BUF;

#pragma unroll
        for (int ks = 0; ks < 4; ++ks) {
            uint32_t ah[4][4], al[4][4], bh[2][4], bl[2][4];
#pragma unroll
            for (int mt = 0; mt < 4; ++mt) {
                const uint32_t so =
                    sw128((uint32_t)(((wm + (mt << 4) + la_r) << 7) + (((ks << 1) + la_c) << 4)));
                ldm_x4(s0 + GSM_AH + so, ah[mt]);
                ldm_x4(s0 + GSM_AL + so, al[mt]);
            }
#pragma unroll
            for (int p = 0; p < 2; ++p) {
                const uint32_t so =
                    sw128((uint32_t)(((wn + (p << 4) + lb_r) << 7) + (((ks << 1) + lb_c) << 4)));
                ldm_x4(s0 + GSM_BH + so, bh[p]);
                ldm_x4(s0 + GSM_BL + so, bl[p]);
            }
#pragma unroll
            for (int mt = 0; mt < 4; ++mt)
#pragma unroll
                for (int nt = 0; nt < 4; ++nt) {
                    const uint32_t* bhp = &bh[nt >> 1][(nt & 1) << 1];
                    const uint32_t* blp = &bl[nt >> 1][(nt & 1) << 1];
                    mma16816(acc[mt][nt], ah[mt], bhp);
                    mma16816(acc[mt][nt], ah[mt], blp);
                    mma16816(acc[mt][nt], al[mt], bhp);
                }
        }
        __syncthreads();
    }

    // epilogue: thread (g,tg) holds cols tg*2, rows g and g+8 per (mt,nt) tile
    const int g = lane >> 2, tg = lane & 3;
#pragma unroll
    for (int mt = 0; mt < 4; ++mt)
#pragma unroll
        for (int nt = 0; nt < 4; ++nt) {
            const int row = row0 + wm + (mt << 4) + g;
            const int col = col0 + wn + (nt << 3) + (tg << 1);
            *(float2*)(C + (size_t)row * N + col) = make_float2(acc[mt][nt][0], acc[mt][nt][1]);
            *(float2*)(C + (size_t)(row + 8) * N + col) = make_float2(acc[mt][nt][2], acc[mt][nt][3]);
        }
}

// ---------------------------------------------------------------------------
// LayerNorm over head_dim=64 for q and k slices of qkv, in place.
// ---------------------------------------------------------------------------
__global__ __launch_bounds__(256) void ln_kernel(
    float* __restrict__ qkv,
    const float* __restrict__ qs, const float* __restrict__ qb,
    const float* __restrict__ ks, const float* __restrict__ kb)
{
    const int w = (int)((blockIdx.x * 256u + threadIdx.x) >> 5);
    const int lane = threadIdx.x & 31;
    const int NQ = TB * TS * TH;
    if (w >= 2 * NQ) return;
    const bool isK = w >= NQ;
    const int r = isK ? (w - NQ) : w;
    const int h = r & 15;
    const int bs = r >> 4;
    float* p = qkv + (size_t)bs * 3072 + (isK ? 1024 : 0) + h * 64 + lane * 2;
    const float* sc = (isK ? ks : qs) + lane * 2;
    const float* bi = (isK ? kb : qb) + lane * 2;

    float2 v = *(const float2*)p;
    float s = v.x + v.y;
    float sq = v.x * v.x + v.y * v.y;
#pragma unroll
    for (int off = 16; off; off >>= 1) {
        s  += __shfl_xor_sync(0xffffffffu, s, off);
        sq += __shfl_xor_sync(0xffffffffu, sq, off);
    }
    float mean = s * (1.f / 64.f);
    float var = fmaxf(sq * (1.f / 64.f) - mean * mean, 0.f);
    float rstd = rsqrtf(var + 1e-5f);
    float2 o;
    o.x = (v.x - mean) * rstd * sc[0] + bi[0];
    o.y = (v.y - mean) * rstd * sc[1] + bi[1];
    *(float2*)p = o;
}

__global__ void zero4_kernel(float* p) { p[threadIdx.x] = 0.f; }

// ---------------------------------------------------------------------------
// Flash attention + streaming entropy (unchanged from R1).
// ---------------------------------------------------------------------------
__global__ __launch_bounds__(256) void attn_kernel(
    const float* __restrict__ qkv, float* __restrict__ ctx, float* __restrict__ ent)
{
    __shared__ float Qt[4096];
    __shared__ float KP[4096];
    __shared__ float Vs[4096];

    const int tid = threadIdx.x;
    const int tx = tid & 15;
    const int ty = tid >> 4;
    const int qb0 = blockIdx.x << 6;
    const int h = blockIdx.y;
    const int b = blockIdx.z;
    const float inv = 0.125f;

    const size_t base = (size_t)b * TS * 3072 + h * 64;

    {
        const int r = tid >> 4;
        const int d0 = (tid & 15) << 2;
#pragma unroll
        for (int rr = 0; rr < 4; ++rr) {
            int row = (rr << 4) + r;
            float4 v = *(const float4*)(qkv + base + (size_t)(qb0 + row) * 3072 + d0);
            int g = row >> 2, ri = row & 3;
            Qt[(d0 + 0) * 64 + ((g ^ ((d0 + 0) & 15)) << 2) + ri] = v.x * inv;
            Qt[(d0 + 1) * 64 + ((g ^ ((d0 + 1) & 15)) << 2) + ri] = v.y * inv;
            Qt[(d0 + 2) * 64 + ((g ^ ((d0 + 2) & 15)) << 2) + ri] = v.z * inv;
            Qt[(d0 + 3) * 64 + ((g ^ ((d0 + 3) & 15)) << 2) + ri] = v.w * inv;
        }
    }

    float o[4][4];
    float m[4], l[4], Tacc[4];
#pragma unroll
    for (int i = 0; i < 4; ++i) {
        m[i] = -1e30f; l[i] = 0.f; Tacc[i] = 0.f;
#pragma unroll
        for (int j = 0; j < 4; ++j) o[i][j] = 0.f;
    }

    for (int kt = 0; kt < TS / 64; ++kt) {
        __syncthreads();
        {
            const int r = tid >> 4;
            const int d0 = (tid & 15) << 2;
#pragma unroll
            for (int rr = 0; rr < 4; ++rr) {
                int row = (rr << 4) + r;
                const float* gp = qkv + base + (size_t)(kt * 64 + row) * 3072 + d0;
                float4 kv = *(const float4*)(gp + 1024);
                float4 vv = *(const float4*)(gp + 2048);
                int g = row >> 2, ri = row & 3;
                KP[(d0 + 0) * 64 + ((g ^ ((d0 + 0) & 15)) << 2) + ri] = kv.x;
                KP[(d0 + 1) * 64 + ((g ^ ((d0 + 1) & 15)) << 2) + ri] = kv.y;
                KP[(d0 + 2) * 64 + ((g ^ ((d0 + 2) & 15)) << 2) + ri] = kv.z;
                KP[(d0 + 3) * 64 + ((g ^ ((d0 + 3) & 15)) << 2) + ri] = kv.w;
                *(float4*)&Vs[row * 64 + d0] = vv;
            }
        }
        __syncthreads();

        float s4[4][4];
#pragma unroll
        for (int i = 0; i < 4; ++i)
#pragma unroll
            for (int j = 0; j < 4; ++j) s4[i][j] = 0.f;

#pragma unroll 8
        for (int d = 0; d < 64; ++d) {
            float4 aq = *(const float4*)&Qt[d * 64 + ((ty ^ (d & 15)) << 2)];
            float4 bk = *(const float4*)&KP[d * 64 + ((tx ^ (d & 15)) << 2)];
            float av[4] = {aq.x, aq.y, aq.z, aq.w};
            float bv[4] = {bk.x, bk.y, bk.z, bk.w};
#pragma unroll
            for (int i = 0; i < 4; ++i)
#pragma unroll
                for (int j = 0; j < 4; ++j)
                    s4[i][j] = fmaf(av[i], bv[j], s4[i][j]);
        }

        float p4[4][4];
#pragma unroll
        for (int i = 0; i < 4; ++i) {
            float mm = fmaxf(fmaxf(s4[i][0], s4[i][1]), fmaxf(s4[i][2], s4[i][3]));
#pragma unroll
            for (int off = 8; off; off >>= 1)
                mm = fmaxf(mm, __shfl_xor_sync(0xffffffffu, mm, off));
            float mn = fmaxf(m[i], mm);
            float lsum = 0.f, tsum = 0.f;
#pragma unroll
            for (int j = 0; j < 4; ++j) {
                float dd = s4[i][j] - mn;
                float e = __expf(dd);
                p4[i][j] = e;
                lsum += e;
                tsum = fmaf(e, dd, tsum);
            }
#pragma unroll
            for (int off = 8; off; off >>= 1) {
                lsum += __shfl_xor_sync(0xffffffffu, lsum, off);
                tsum += __shfl_xor_sync(0xffffffffu, tsum, off);
            }
            float dm = mn - m[i];
            float corr = __expf(-dm);
            Tacc[i] = fmaf(corr, Tacc[i] - dm * l[i], tsum);
            l[i] = fmaf(l[i], corr, lsum);
            m[i] = mn;
#pragma unroll
            for (int j = 0; j < 4; ++j) o[i][j] *= corr;
        }

        __syncthreads();
#pragma unroll
        for (int i = 0; i < 4; ++i)
            *(float4*)&KP[((ty << 2) + i) * 64 + (tx << 2)] =
                make_float4(p4[i][0], p4[i][1], p4[i][2], p4[i][3]);
        __syncthreads();

#pragma unroll 4
        for (int k0 = 0; k0 < 64; k0 += 4) {
            float4 pa[4], vb[4];
#pragma unroll
            for (int i = 0; i < 4; ++i)
                pa[i] = *(const float4*)&KP[((ty << 2) + i) * 64 + k0];
#pragma unroll
            for (int kk = 0; kk < 4; ++kk)
                vb[kk] = *(const float4*)&Vs[(k0 + kk) * 64 + (tx << 2)];
#pragma unroll
            for (int i = 0; i < 4; ++i) {
                float pav[4] = {pa[i].x, pa[i].y, pa[i].z, pa[i].w};
#pragma unroll
                for (int kk = 0; kk < 4; ++kk) {
                    float vbv[4] = {vb[kk].x, vb[kk].y, vb[kk].z, vb[kk].w};
#pragma unroll
                    for (int j = 0; j < 4; ++j)
                        o[i][j] = fmaf(pav[kk], vbv[j], o[i][j]);
                }
            }
        }
    }

#pragma unroll
    for (int i = 0; i < 4; ++i) {
        float rl = 1.f / l[i];
        int q = qb0 + (ty << 2) + i;
        *(float4*)(ctx + (size_t)(b * TS + q) * 1024 + h * 64 + (tx << 2)) =
            make_float4(o[i][0] * rl, o[i][1] * rl, o[i][2] * rl, o[i][3] * rl);
    }

    __syncthreads();
    float* red = Vs;
    if (tx == 0) {
        float e = 0.f;
#pragma unroll
        for (int i = 0; i < 4; ++i) e += __logf(l[i]) - Tacc[i] / l[i];
        red[ty] = e;
    }
    __syncthreads();
    if (tid == 0) {
        float e = 0.f;
#pragma unroll
        for (int i = 0; i < 16; ++i) e += red[i];
        const float ent_scale = (float)(1.0 / (7.6246189861593985 * (double)(TH * TS)));
        atomicAdd(ent + b, e * ent_scale);
    }
}

// ---------------------------------------------------------------------------
extern "C" void kernel_launch(void* const* d_in, const int* in_sizes, int n_in,
                              void* d_out, int out_size)
{
    const float* x       = (const float*)d_in[0];
    const float* w_qkv   = (const float*)d_in[1];
    const float* w_proj  = (const float*)d_in[2];
    const float* q_scale = (const float*)d_in[3];
    const float* q_bias  = (const float*)d_in[4];
    const float* k_scale = (const float*)d_in[5];
    const float* k_bias  = (const float*)d_in[6];
    float* out = (float*)d_out;

    float *qkv, *ctx, *entpad;
    cudaGetSymbolAddress((void**)&qkv, g_qkv);
    cudaGetSymbolAddress((void**)&ctx, g_ctx);
    cudaGetSymbolAddress((void**)&entpad, g_entpad);
    __nv_bfloat16 *xh, *xl, *wqh, *wql, *ch, *cl, *wph, *wpl;
    cudaGetSymbolAddress((void**)&xh, g_xh);
    cudaGetSymbolAddress((void**)&xl, g_xl);
    cudaGetSymbolAddress((void**)&wqh, g_wqh);
    cudaGetSymbolAddress((void**)&wql, g_wql);
    cudaGetSymbolAddress((void**)&ch, g_ch);
    cudaGetSymbolAddress((void**)&cl, g_cl);
    cudaGetSymbolAddress((void**)&wph, g_wph);
    cudaGetSymbolAddress((void**)&wpl, g_wpl);

    cudaFuncSetAttribute(gemm_mma_kernel, cudaFuncAttributeMaxDynamicSharedMemorySize, GEMM_SMEM);

    const int BS = TB * TS;                 // 8192
    const size_t main_elems = (size_t)BS * TC;
    float* ent = (out_size >= (int)(main_elems + TB)) ? (out + main_elems) : entpad;

    // 1) split x -> bf16 hi/lo ; transpose+split w_qkv
    {
        int n4 = (BS * TC) / 4;
        split_kernel<<<(n4 + 255) / 256, 256>>>((const float4*)x, xh, xl, n4);
        splitT_kernel<<<dim3(3 * TC / 32, TC / 32), dim3(32, 8)>>>(w_qkv, wqh, wql, TC, 3 * TC);
    }

    // 2) QKV projection on tensor cores (mma.sync): [8192,1024] @ [1024,3072]
    gemm_mma_kernel<<<dim3(3 * TC / 128, BS / 128), 256, GEMM_SMEM>>>(
        xh, xl, wqh, wql, qkv, BS, 3 * TC, TC);

    // 3) LayerNorm q,k
    ln_kernel<<<(2 * TB * TS * TH) / 8, 256>>>(qkv, q_scale, q_bias, k_scale, k_bias);

    // 4) zero entropy accumulators
    zero4_kernel<<<1, TB>>>(ent);

    // 5) fused attention + entropy -> ctx
    attn_kernel<<<dim3(TS / 64, TH, TB), 256>>>(qkv, ctx, ent);

    // 6) split ctx ; transpose+split w_proj
    {
        int n4 = (BS * TC) / 4;
        split_kernel<<<(n4 + 255) / 256, 256>>>((const float4*)ctx, ch, cl, n4);
        splitT_kernel<<<dim3(TC / 32, TC / 32), dim3(32, 8)>>>(w_proj, wph, wpl, TC, TC);
    }

    // 7) output projection on tensor cores: [8192,1024] @ [1024,1024]
    gemm_mma_kernel<<<dim3(TC / 128, BS / 128), 256, GEMM_SMEM>>>(
        ch, cl, wph, wpl, out, BS, TC, TC);
}

// round 4
// speedup vs baseline: 2.8782x; 2.1558x over previous
#include <cuda_runtime.h>
#include <cuda_bf16.h>
#include <cstdint>

#define TB 4
#define TS 2048
#define TH 16
#define TD 64
#define TC 1024

// ---------------------------------------------------------------------------
// Scratch (alloc-free rule: __device__ globals)
// ---------------------------------------------------------------------------
static __device__ float g_qkv[(size_t)8192 * 3072];          // [B*S, 3*C] fp32
static __device__ float g_ctx[(size_t)8192 * 1024];          // [B*S, C]   fp32
static __device__ float g_entpad[4];
// bf16 split operands
static __device__ __nv_bfloat16 g_xh[(size_t)8192 * 1024];
static __device__ __nv_bfloat16 g_xl[(size_t)8192 * 1024];
static __device__ __nv_bfloat16 g_wqh[(size_t)3072 * 1024];  // w_qkv^T [N,K]
static __device__ __nv_bfloat16 g_wql[(size_t)3072 * 1024];
static __device__ __nv_bfloat16 g_ch[(size_t)8192 * 1024];
static __device__ __nv_bfloat16 g_cl[(size_t)8192 * 1024];
static __device__ __nv_bfloat16 g_wph[(size_t)1024 * 1024];  // w_proj^T [N,K]
static __device__ __nv_bfloat16 g_wpl[(size_t)1024 * 1024];

// ---------------------------------------------------------------------------
// Helpers (sm_103 base target: ldmatrix + mma.sync + cp.async only)
// ---------------------------------------------------------------------------
__device__ __forceinline__ uint32_t smem_u32(const void* p) {
    uint32_t a;
    asm("{ .reg .u64 t; cvta.to.shared.u64 t, %1; cvt.u32.u64 %0, t; }" : "=r"(a) : "l"(p));
    return a;
}
__device__ __forceinline__ uint32_t sw128(uint32_t off) { return off ^ ((off >> 3) & 0x70); }

__device__ __forceinline__ void cp16(uint32_t saddr, const void* gptr) {
    asm volatile("cp.async.cg.shared.global [%0], [%1], 16;" :: "r"(saddr), "l"(gptr));
}
__device__ __forceinline__ void cp_commit() {
    asm volatile("cp.async.commit_group;" ::: "memory");
}
template <int N>
__device__ __forceinline__ void cp_wait() {
    asm volatile("cp.async.wait_group %0;" :: "n"(N) : "memory");
}

__device__ __forceinline__ void ldm_x4(uint32_t addr, uint32_t r[4]) {
    asm volatile("ldmatrix.sync.aligned.m8n8.x4.shared.b16 {%0,%1,%2,%3}, [%4];"
                 : "=r"(r[0]), "=r"(r[1]), "=r"(r[2]), "=r"(r[3]) : "r"(addr));
}
__device__ __forceinline__ void ldm_x4_t(uint32_t addr, uint32_t r[4]) {
    asm volatile("ldmatrix.sync.aligned.m8n8.x4.trans.shared.b16 {%0,%1,%2,%3}, [%4];"
                 : "=r"(r[0]), "=r"(r[1]), "=r"(r[2]), "=r"(r[3]) : "r"(addr));
}

__device__ __forceinline__ void mma16816(float d[4], const uint32_t a[4], const uint32_t b[2]) {
    asm volatile(
        "mma.sync.aligned.m16n8k16.row.col.f32.bf16.bf16.f32 "
        "{%0,%1,%2,%3}, {%4,%5,%6,%7}, {%8,%9}, {%0,%1,%2,%3};"
        : "+f"(d[0]), "+f"(d[1]), "+f"(d[2]), "+f"(d[3])
        : "r"(a[0]), "r"(a[1]), "r"(a[2]), "r"(a[3]), "r"(b[0]), "r"(b[1]));
}

// split two floats into packed bf16x2 hi + lo halves (hi.x = first)
__device__ __forceinline__ void split2(float a, float b, uint32_t& hi, uint32_t& lo) {
    __nv_bfloat162 h = __floats2bfloat162_rn(a, b);
    float ra = a - __bfloat162float(h.x);
    float rb = b - __bfloat162float(h.y);
    __nv_bfloat162 l = __floats2bfloat162_rn(ra, rb);
    hi = *(uint32_t*)&h;
    lo = *(uint32_t*)&l;
}

// ---------------------------------------------------------------------------
// Split-precision conversion kernels
// ---------------------------------------------------------------------------
__device__ __forceinline__ void split_one(float v, __nv_bfloat16& h, __nv_bfloat16& l) {
    h = __float2bfloat16_rn(v);
    l = __float2bfloat16_rn(v - __bfloat162float(h));
}

__global__ __launch_bounds__(256) void split_kernel(
    const float4* __restrict__ in, __nv_bfloat16* __restrict__ hi,
    __nv_bfloat16* __restrict__ lo, int n4)
{
    int i = blockIdx.x * 256 + threadIdx.x;
    if (i >= n4) return;
    float4 v = in[i];
    uint32_t h01, h23, l01, l23;
    split2(v.x, v.y, h01, l01);
    split2(v.z, v.w, h23, l23);
    ((uint2*)hi)[i] = make_uint2(h01, h23);
    ((uint2*)lo)[i] = make_uint2(l01, l23);
}

// Transpose + split: in f32 [K,N] -> hi/lo bf16 [N,K]
__global__ __launch_bounds__(256) void splitT_kernel(
    const float* __restrict__ in, __nv_bfloat16* __restrict__ hi,
    __nv_bfloat16* __restrict__ lo, int K, int N)
{
    __shared__ float t[32][33];
    const int n0 = blockIdx.x << 5;
    const int k0 = blockIdx.y << 5;
    const int tx = threadIdx.x, ty = threadIdx.y;   // 32 x 8
#pragma unroll
    for (int j = 0; j < 32; j += 8)
        t[ty + j][tx] = in[(size_t)(k0 + ty + j) * N + n0 + tx];
    __syncthreads();
#pragma unroll
    for (int j = 0; j < 32; j += 8) {
        float v = t[tx][ty + j];
        __nv_bfloat16 h, l;
        split_one(v, h, l);
        size_t o = (size_t)(n0 + ty + j) * K + k0 + tx;
        hi[o] = h;
        lo[o] = l;
    }
}

// ---------------------------------------------------------------------------
// Warp-MMA bf16x3 GEMM (unchanged from R3): C[M,N] = A[M,K] @ Bt[N,K]^T
// ---------------------------------------------------------------------------
#define GSM_AH 0
#define GSM_AL 16384
#define GSM_BH 32768
#define GSM_BL 49152
#define GSM_BUF 65536
#define GEMM_SMEM (2 * GSM_BUF)

__global__ __launch_bounds__(256) void gemm_mma_kernel(
    const __nv_bfloat16* __restrict__ Ah, const __nv_bfloat16* __restrict__ Al,
    const __nv_bfloat16* __restrict__ Bh, const __nv_bfloat16* __restrict__ Bl,
    float* __restrict__ C, int M, int N, int K)
{
    extern __shared__ char smem[];
    const uint32_t sb = smem_u32(smem);
    const int tid = threadIdx.x;
    const int wid = tid >> 5;
    const int lane = tid & 31;
    const int row0 = blockIdx.y << 7;
    const int col0 = blockIdx.x << 7;
    const int wm = (wid & 1) << 6;
    const int wn = (wid >> 1) << 5;

    const int lr0 = tid >> 1;
    const int lk0 = (tid & 1) << 2;

    float acc[4][4][4];
#pragma unroll
    for (int mt = 0; mt < 4; ++mt)
#pragma unroll
        for (int nt = 0; nt < 4; ++nt)
#pragma unroll
            for (int r = 0; r < 4; ++r) acc[mt][nt][r] = 0.f;

    const int nk = K >> 6;

    auto load_tile = [&](int kb, int buf) {
        const uint32_t s0 = sb + buf * GSM_BUF;
#pragma unroll
        for (int cc = 0; cc < 4; ++cc) {
            const int r = lr0;
            const int k8 = lk0 + cc;
            const size_t offA = (size_t)(row0 + r) * K + kb + (k8 << 3);
            const size_t offB = (size_t)(col0 + r) * K + kb + (k8 << 3);
            const uint32_t so = sw128((uint32_t)((r << 7) + (k8 << 4)));
            cp16(s0 + GSM_AH + so, Ah + offA);
            cp16(s0 + GSM_AL + so, Al + offA);
            cp16(s0 + GSM_BH + so, Bh + offB);
            cp16(s0 + GSM_BL + so, Bl + offB);
        }
        cp_commit();
    };

    load_tile(0, 0);

    const int la_r = lane & 15;
    const int la_c = lane >> 4;
    const int lb_r = ((lane >> 4) << 3) + (lane & 7);
    const int lb_c = (lane >> 3) & 1;

    for (int it = 0; it < nk; ++it) {
        if (it + 1 < nk) { load_tile((it + 1) << 6, (it + 1) & 1); cp_wait<1>(); }
        else             { cp_wait<0>(); }
        __syncthreads();
        const uint32_t s0 = sb + (it & 1) * GSM_BUF;

#pragma unroll
        for (int ks = 0; ks < 4; ++ks) {
            uint32_t ah[4][4], al[4][4], bh[2][4], bl[2][4];
#pragma unroll
            for (int mt = 0; mt < 4; ++mt) {
                const uint32_t so =
                    sw128((uint32_t)(((wm + (mt << 4) + la_r) << 7) + (((ks << 1) + la_c) << 4)));
                ldm_x4(s0 + GSM_AH + so, ah[mt]);
                ldm_x4(s0 + GSM_AL + so, al[mt]);
            }
#pragma unroll
            for (int p = 0; p < 2; ++p) {
                const uint32_t so =
                    sw128((uint32_t)(((wn + (p << 4) + lb_r) << 7) + (((ks << 1) + lb_c) << 4)));
                ldm_x4(s0 + GSM_BH + so, bh[p]);
                ldm_x4(s0 + GSM_BL + so, bl[p]);
            }
#pragma unroll
            for (int mt = 0; mt < 4; ++mt)
#pragma unroll
                for (int nt = 0; nt < 4; ++nt) {
                    const uint32_t* bhp = &bh[nt >> 1][(nt & 1) << 1];
                    const uint32_t* blp = &bl[nt >> 1][(nt & 1) << 1];
                    mma16816(acc[mt][nt], ah[mt], bhp);
                    mma16816(acc[mt][nt], ah[mt], blp);
                    mma16816(acc[mt][nt], al[mt], bhp);
                }
        }
        __syncthreads();
    }

    const int g = lane >> 2, tg = lane & 3;
#pragma unroll
    for (int mt = 0; mt < 4; ++mt)
#pragma unroll
        for (int nt = 0; nt < 4; ++nt) {
            const int row = row0 + wm + (mt << 4) + g;
            const int col = col0 + wn + (nt << 3) + (tg << 1);
            *(float2*)(C + (size_t)row * N + col) = make_float2(acc[mt][nt][0], acc[mt][nt][1]);
            *(float2*)(C + (size_t)(row + 8) * N + col) = make_float2(acc[mt][nt][2], acc[mt][nt][3]);
        }
}

// ---------------------------------------------------------------------------
// LayerNorm over head_dim=64 for q and k slices of qkv, in place.
// ---------------------------------------------------------------------------
__global__ __launch_bounds__(256) void ln_kernel(
    float* __restrict__ qkv,
    const float* __restrict__ qs, const float* __restrict__ qb,
    const float* __restrict__ ks, const float* __restrict__ kb)
{
    const int w = (int)((blockIdx.x * 256u + threadIdx.x) >> 5);
    const int lane = threadIdx.x & 31;
    const int NQ = TB * TS * TH;
    if (w >= 2 * NQ) return;
    const bool isK = w >= NQ;
    const int r = isK ? (w - NQ) : w;
    const int h = r & 15;
    const int bs = r >> 4;
    float* p = qkv + (size_t)bs * 3072 + (isK ? 1024 : 0) + h * 64 + lane * 2;
    const float* sc = (isK ? ks : qs) + lane * 2;
    const float* bi = (isK ? kb : qb) + lane * 2;

    float2 v = *(const float2*)p;
    float s = v.x + v.y;
    float sq = v.x * v.x + v.y * v.y;
#pragma unroll
    for (int off = 16; off; off >>= 1) {
        s  += __shfl_xor_sync(0xffffffffu, s, off);
        sq += __shfl_xor_sync(0xffffffffu, sq, off);
    }
    float mean = s * (1.f / 64.f);
    float var = fmaxf(sq * (1.f / 64.f) - mean * mean, 0.f);
    float rstd = rsqrtf(var + 1e-5f);
    float2 o;
    o.x = (v.x - mean) * rstd * sc[0] + bi[0];
    o.y = (v.y - mean) * rstd * sc[1] + bi[1];
    *(float2*)p = o;
}

__global__ void zero4_kernel(float* p) { p[threadIdx.x] = 0.f; }

// ---------------------------------------------------------------------------
// Flash attention on mma.sync (bf16x3) + streaming entropy.
// CTA: 64 q-rows, 4 warps (warp = m16 x n64). K-tile = 64 keys.
// Smem: K hi/lo + V hi/lo, 64x64 bf16 each (8KB x4 = 32KB), SW128 rows.
// Q staged once (scaled by 1/8, split) -> register A-fragments hi/lo.
// S = QhKh+QhKl+QlKh ; online softmax on fragments (quad shfl reductions);
// P split hi/lo in regs (C-frag == A-frag layout) ; O += PhVh+PhVl+PlVh
// with V fed via ldmatrix.trans. Entropy: log(l) - T/l streamed.
// ---------------------------------------------------------------------------
__global__ __launch_bounds__(128) void attn_mma_kernel(
    const float* __restrict__ qkv, float* __restrict__ ctx, float* __restrict__ ent)
{
    __shared__ __align__(16) char smA[32768];
    __shared__ float red[4];
    const uint32_t sb = smem_u32(smA);
    const uint32_t KH = 0, KL = 8192, VH = 16384, VL = 24576;

    const int tid = threadIdx.x, wid = tid >> 5, lane = tid & 31;
    const int qb0 = blockIdx.x << 6;           // 64 q rows per CTA
    const int h = blockIdx.y, b = blockIdx.z;
    const size_t base = (size_t)b * TS * 3072 + h * 64;
    const float inv = 0.125f;                  // 1/sqrt(64), TEMP=1

    // ---- stage Q (scaled+split) into smem [0,8K)=hi, [8K,16K)=lo ----
#pragma unroll
    for (int j = 0; j < 8; ++j) {
        int i = tid + 128 * j;                 // 1024 float4 total
        int row = i >> 4, c4 = i & 15;
        float4 v = *(const float4*)(qkv + base + (size_t)(qb0 + row) * 3072 + c4 * 4);
        uint32_t h01, h23, l01, l23;
        split2(v.x * inv, v.y * inv, h01, l01);
        split2(v.z * inv, v.w * inv, h23, l23);
        uint32_t so = sw128((uint32_t)(row * 128 + c4 * 8));
        *(uint2*)(smA + 0 + so) = make_uint2(h01, h23);
        *(uint2*)(smA + 8192 + so) = make_uint2(l01, l23);
    }
    __syncthreads();

    // ---- load Q A-fragments (hi/lo) for 4 k16 steps ----
    uint32_t qh[4][4], ql[4][4];
    {
        const int row = (wid << 4) + (lane & 15);
        const int cb = (lane >> 4) << 4;       // 0 or 16 bytes (k-half)
#pragma unroll
        for (int s = 0; s < 4; ++s) {
            uint32_t so = sw128((uint32_t)(row * 128 + s * 32 + cb));
            ldm_x4(sb + 0 + so, qh[s]);
            ldm_x4(sb + 8192 + so, ql[s]);
        }
    }

    float o[8][4];
#pragma unroll
    for (int nt = 0; nt < 8; ++nt)
#pragma unroll
        for (int r = 0; r < 4; ++r) o[nt][r] = 0.f;
    float m2[2] = {-1e30f, -1e30f}, l2[2] = {0.f, 0.f}, T2[2] = {0.f, 0.f};

    // precomputed lane addressing pieces
    const int kb_row = ((lane >> 4) << 3) + (lane & 7);   // K b-frag row-in-16
    const int kb_c = (lane >> 3) & 1;                     // K b-frag k-half
    const int v_key = (((lane >> 3) & 1) << 3) + (lane & 7);  // V trans key-in-16
    const int v_d = (lane >> 4) << 3;                     // V trans d offset

    for (int kt = 0; kt < TS / 64; ++kt) {
        __syncthreads();   // previous iteration's smem readers done
        // ---- load K,V tile: 64 rows x 64 d, fp32 -> split -> smem bf16 ----
#pragma unroll
        for (int j = 0; j < 8; ++j) {
            int i = tid + 128 * j;             // 1024 (row,c4) pairs
            int row = i >> 4, c4 = i & 15;
            const float* gp = qkv + base + (size_t)(kt * 64 + row) * 3072 + c4 * 4;
            float4 kv = *(const float4*)(gp + 1024);
            float4 vv = *(const float4*)(gp + 2048);
            uint32_t so = sw128((uint32_t)(row * 128 + c4 * 8));
            uint32_t h01, h23, l01, l23;
            split2(kv.x, kv.y, h01, l01);
            split2(kv.z, kv.w, h23, l23);
            *(uint2*)(smA + KH + so) = make_uint2(h01, h23);
            *(uint2*)(smA + KL + so) = make_uint2(l01, l23);
            split2(vv.x, vv.y, h01, l01);
            split2(vv.z, vv.w, h23, l23);
            *(uint2*)(smA + VH + so) = make_uint2(h01, h23);
            *(uint2*)(smA + VL + so) = make_uint2(l01, l23);
        }
        __syncthreads();

        // ---- S = Q K^T (bf16x3) ----
        float s4[8][4];
#pragma unroll
        for (int nt = 0; nt < 8; ++nt)
#pragma unroll
            for (int r = 0; r < 4; ++r) s4[nt][r] = 0.f;

#pragma unroll
        for (int s = 0; s < 4; ++s) {
            uint32_t kbh[4][4], kbl[4][4];
#pragma unroll
            for (int p = 0; p < 4; ++p) {
                uint32_t so = sw128((uint32_t)(((p << 4) + kb_row) * 128 + s * 32 + kb_c * 16));
                ldm_x4(sb + KH + so, kbh[p]);
                ldm_x4(sb + KL + so, kbl[p]);
            }
#pragma unroll
            for (int nt = 0; nt < 8; ++nt) {
                const uint32_t* bh2 = &kbh[nt >> 1][(nt & 1) << 1];
                const uint32_t* bl2 = &kbl[nt >> 1][(nt & 1) << 1];
                mma16816(s4[nt], qh[s], bh2);
                mma16816(s4[nt], qh[s], bl2);
                mma16816(s4[nt], ql[s], bh2);
            }
        }

        // ---- online softmax + entropy terms (rows g, g+8 per thread) ----
        float mx0 = s4[0][0], mx1 = s4[0][2];
#pragma unroll
        for (int nt = 0; nt < 8; ++nt) {
            mx0 = fmaxf(mx0, fmaxf(s4[nt][0], s4[nt][1]));
            mx1 = fmaxf(mx1, fmaxf(s4[nt][2], s4[nt][3]));
        }
#pragma unroll
        for (int off = 1; off <= 2; off <<= 1) {
            mx0 = fmaxf(mx0, __shfl_xor_sync(0xffffffffu, mx0, off));
            mx1 = fmaxf(mx1, __shfl_xor_sync(0xffffffffu, mx1, off));
        }
        float mn0 = fmaxf(m2[0], mx0), mn1 = fmaxf(m2[1], mx1);
        float ls0 = 0.f, ts0 = 0.f, ls1 = 0.f, ts1 = 0.f;
#pragma unroll
        for (int nt = 0; nt < 8; ++nt) {
            float d0 = s4[nt][0] - mn0, d1 = s4[nt][1] - mn0;
            float d2 = s4[nt][2] - mn1, d3 = s4[nt][3] - mn1;
            float e0 = __expf(d0), e1 = __expf(d1), e2 = __expf(d2), e3 = __expf(d3);
            s4[nt][0] = e0; s4[nt][1] = e1; s4[nt][2] = e2; s4[nt][3] = e3;
            ls0 += e0 + e1; ls1 += e2 + e3;
            ts0 = fmaf(e0, d0, fmaf(e1, d1, ts0));
            ts1 = fmaf(e2, d2, fmaf(e3, d3, ts1));
        }
#pragma unroll
        for (int off = 1; off <= 2; off <<= 1) {
            ls0 += __shfl_xor_sync(0xffffffffu, ls0, off);
            ts0 += __shfl_xor_sync(0xffffffffu, ts0, off);
            ls1 += __shfl_xor_sync(0xffffffffu, ls1, off);
            ts1 += __shfl_xor_sync(0xffffffffu, ts1, off);
        }
        float dm0 = mn0 - m2[0], c0 = __expf(-dm0);
        float dm1 = mn1 - m2[1], c1 = __expf(-dm1);
        T2[0] = fmaf(c0, T2[0] - dm0 * l2[0], ts0);
        T2[1] = fmaf(c1, T2[1] - dm1 * l2[1], ts1);
        l2[0] = fmaf(l2[0], c0, ls0);
        l2[1] = fmaf(l2[1], c1, ls1);
        m2[0] = mn0; m2[1] = mn1;
#pragma unroll
        for (int nt = 0; nt < 8; ++nt) {
            o[nt][0] *= c0; o[nt][1] *= c0;
            o[nt][2] *= c1; o[nt][3] *= c1;
        }

        // ---- O += P V (bf16x3; P from frags, V via ldmatrix.trans) ----
#pragma unroll
        for (int s = 0; s < 4; ++s) {
            uint32_t pah[4], pal[4];
            split2(s4[2 * s][0],     s4[2 * s][1],     pah[0], pal[0]);
            split2(s4[2 * s][2],     s4[2 * s][3],     pah[1], pal[1]);
            split2(s4[2 * s + 1][0], s4[2 * s + 1][1], pah[2], pal[2]);
            split2(s4[2 * s + 1][2], s4[2 * s + 1][3], pah[3], pal[3]);
            uint32_t vbh[4][4], vbl[4][4];
#pragma unroll
            for (int p2 = 0; p2 < 4; ++p2) {
                uint32_t so = sw128((uint32_t)(((s << 4) + v_key) * 128 + ((p2 << 4) + v_d) * 2));
                ldm_x4_t(sb + VH + so, vbh[p2]);
                ldm_x4_t(sb + VL + so, vbl[p2]);
            }
#pragma unroll
            for (int nt = 0; nt < 8; ++nt) {
                const uint32_t* bh2 = &vbh[nt >> 1][(nt & 1) << 1];
                const uint32_t* bl2 = &vbl[nt >> 1][(nt & 1) << 1];
                mma16816(o[nt], pah, bh2);
                mma16816(o[nt], pah, bl2);
                mma16816(o[nt], pal, bh2);
            }
        }
    }

    // ---- write context (normalize by l) ----
    {
        float rl0 = 1.f / l2[0], rl1 = 1.f / l2[1];
        const int r0 = qb0 + (wid << 4) + (lane >> 2);
        const int cb = (h << 6) + ((lane & 3) << 1);
#pragma unroll
        for (int nt = 0; nt < 8; ++nt) {
            const int col = cb + (nt << 3);
            *(float2*)(ctx + (size_t)(b * TS + r0) * 1024 + col) =
                make_float2(o[nt][0] * rl0, o[nt][1] * rl0);
            *(float2*)(ctx + (size_t)(b * TS + r0 + 8) * 1024 + col) =
                make_float2(o[nt][2] * rl1, o[nt][3] * rl1);
        }
    }

    // ---- entropy: per-row log(l) - T/l, reduce, one atomic per CTA ----
    float e = 0.f;
    if ((lane & 3) == 0)
        e = (__logf(l2[0]) - T2[0] / l2[0]) + (__logf(l2[1]) - T2[1] / l2[1]);
#pragma unroll
    for (int off = 16; off; off >>= 1) e += __shfl_xor_sync(0xffffffffu, e, off);
    if (lane == 0) red[wid] = e;
    __syncthreads();
    if (tid == 0) {
        float esum = red[0] + red[1] + red[2] + red[3];
        const float ent_scale = (float)(1.0 / (7.6246189861593985 * (double)(TH * TS)));
        atomicAdd(ent + b, esum * ent_scale);
    }
}

// ---------------------------------------------------------------------------
extern "C" void kernel_launch(void* const* d_in, const int* in_sizes, int n_in,
                              void* d_out, int out_size)
{
    const float* x       = (const float*)d_in[0];
    const float* w_qkv   = (const float*)d_in[1];
    const float* w_proj  = (const float*)d_in[2];
    const float* q_scale = (const float*)d_in[3];
    const float* q_bias  = (const float*)d_in[4];
    const float* k_scale = (const float*)d_in[5];
    const float* k_bias  = (const float*)d_in[6];
    float* out = (float*)d_out;

    float *qkv, *ctx, *entpad;
    cudaGetSymbolAddress((void**)&qkv, g_qkv);
    cudaGetSymbolAddress((void**)&ctx, g_ctx);
    cudaGetSymbolAddress((void**)&entpad, g_entpad);
    __nv_bfloat16 *xh, *xl, *wqh, *wql, *ch, *cl, *wph, *wpl;
    cudaGetSymbolAddress((void**)&xh, g_xh);
    cudaGetSymbolAddress((void**)&xl, g_xl);
    cudaGetSymbolAddress((void**)&wqh, g_wqh);
    cudaGetSymbolAddress((void**)&wql, g_wql);
    cudaGetSymbolAddress((void**)&ch, g_ch);
    cudaGetSymbolAddress((void**)&cl, g_cl);
    cudaGetSymbolAddress((void**)&wph, g_wph);
    cudaGetSymbolAddress((void**)&wpl, g_wpl);

    cudaFuncSetAttribute(gemm_mma_kernel, cudaFuncAttributeMaxDynamicSharedMemorySize, GEMM_SMEM);

    const int BS = TB * TS;                 // 8192
    const size_t main_elems = (size_t)BS * TC;
    float* ent = (out_size >= (int)(main_elems + TB)) ? (out + main_elems) : entpad;

    // 1) split x -> bf16 hi/lo ; transpose+split w_qkv
    {
        int n4 = (BS * TC) / 4;
        split_kernel<<<(n4 + 255) / 256, 256>>>((const float4*)x, xh, xl, n4);
        splitT_kernel<<<dim3(3 * TC / 32, TC / 32), dim3(32, 8)>>>(w_qkv, wqh, wql, TC, 3 * TC);
    }

    // 2) QKV projection on tensor cores (mma.sync): [8192,1024] @ [1024,3072]
    gemm_mma_kernel<<<dim3(3 * TC / 128, BS / 128), 256, GEMM_SMEM>>>(
        xh, xl, wqh, wql, qkv, BS, 3 * TC, TC);

    // 3) LayerNorm q,k
    ln_kernel<<<(2 * TB * TS * TH) / 8, 256>>>(qkv, q_scale, q_bias, k_scale, k_bias);

    // 4) zero entropy accumulators
    zero4_kernel<<<1, TB>>>(ent);

    // 5) fused attention + entropy -> ctx (tensor-core path)
    attn_mma_kernel<<<dim3(TS / 64, TH, TB), 128>>>(qkv, ctx, ent);

    // 6) split ctx ; transpose+split w_proj
    {
        int n4 = (BS * TC) / 4;
        split_kernel<<<(n4 + 255) / 256, 256>>>((const float4*)ctx, ch, cl, n4);
        splitT_kernel<<<dim3(TC / 32, TC / 32), dim3(32, 8)>>>(w_proj, wph, wpl, TC, TC);
    }

    // 7) output projection on tensor cores: [8192,1024] @ [1024,1024]
    gemm_mma_kernel<<<dim3(TC / 128, BS / 128), 256, GEMM_SMEM>>>(
        ch, cl, wph, wpl, out, BS, TC, TC);
}